// round 4
// baseline (speedup 1.0000x reference)
#include <cuda_runtime.h>

#define NROWS 8192
#define D     4096
#define NT    256
#define PER   16   // elements per thread

// Precomputed g = g_mu + softplus(g_rho) * epsilon (same for every row)
__device__ float g_buf[D];

__global__ void prep_g_kernel(const float* __restrict__ g_mu,
                              const float* __restrict__ g_rho,
                              const float* __restrict__ eps) {
    int i = blockIdx.x * blockDim.x + threadIdx.x;
    if (i < D) {
        float x  = g_rho[i];
        // numerically stable softplus
        float sp = fmaxf(x, 0.0f) + log1pf(expf(-fabsf(x)));
        g_buf[i] = g_mu[i] + sp * eps[i];
    }
}

__device__ __forceinline__ int pad(int i) { return i + (i >> 5); }

// Butterfly over a register-index bit
__device__ __forceinline__ void reg_stage(float* r, int bit) {
#pragma unroll
    for (int j = 0; j < PER; j++) {
        if (!(j & bit)) {
            float a = r[j], b = r[j | bit];
            r[j]       = a + b;
            r[j | bit] = a - b;
        }
    }
}

// Butterfly over a lane bit via shfl_xor (applies to all PER regs)
__device__ __forceinline__ void shfl_stage(float* r, int mask, int lane) {
    bool hi = (lane & mask) != 0;
#pragma unroll
    for (int j = 0; j < PER; j++) {
        float o = __shfl_xor_sync(0xffffffffu, r[j], mask);
        r[j] = hi ? (o - r[j]) : (o + r[j]);
    }
}

__global__ __launch_bounds__(NT) void whvi_kernel(const float* __restrict__ x,
                                                  const float* __restrict__ s1,
                                                  const float* __restrict__ s2,
                                                  float* __restrict__ out) {
    __shared__ float sm[D + D / 32];  // padded: addr(i) = i + (i>>5)

    const int t    = threadIdx.x;
    const int lane = t & 31;
    const size_t rowoff = (size_t)blockIdx.x * D;
    const float* __restrict__ xr = x + rowoff;
    float* __restrict__ orow     = out + rowoff;

    float r[PER];

    // Load (layout A: r[j] = element i = j*256 + t), fused *s2. Coalesced.
#pragma unroll
    for (int j = 0; j < PER; j++) {
        int i = j * NT + t;
        r[j] = xr[i] * __ldg(&s2[i]);
    }

    // ---------------- FWHT #1 ----------------
    // i-bits 8..11 live in register index j
    reg_stage(r, 1); reg_stage(r, 2); reg_stage(r, 4); reg_stage(r, 8);
    // i-bits 0..4 live in lane bits
    shfl_stage(r, 1, lane);  shfl_stage(r, 2, lane);  shfl_stage(r, 4, lane);
    shfl_stage(r, 8, lane);  shfl_stage(r, 16, lane);

    // Transpose: layout A (i = j*256+t) -> layout B (i = t*16+j)
#pragma unroll
    for (int j = 0; j < PER; j++) sm[pad(j * NT + t)] = r[j];
    __syncthreads();
#pragma unroll
    for (int j = 0; j < PER; j++) r[j] = sm[pad(t * PER + j)];

    // Remaining i-bits 5..7 are now lane bits 1..3
    shfl_stage(r, 2, lane); shfl_stage(r, 4, lane); shfl_stage(r, 8, lane);

    // -------- elementwise * g (fused g_mu + noise path by linearity) --------
#pragma unroll
    for (int j = 0; j < PER; j++) r[j] *= g_buf[t * PER + j];

    // ---------------- FWHT #2 (starting layout B: i = t*16 + j) ------------
    // i-bits 0..3 = register index
    reg_stage(r, 1); reg_stage(r, 2); reg_stage(r, 4); reg_stage(r, 8);
    // i-bits 4..8 = lane bits 0..4
    shfl_stage(r, 1, lane);  shfl_stage(r, 2, lane);  shfl_stage(r, 4, lane);
    shfl_stage(r, 8, lane);  shfl_stage(r, 16, lane);

    __syncthreads();  // all layout-B reads done before smem reuse
    // Transpose back: layout B -> layout A
#pragma unroll
    for (int j = 0; j < PER; j++) sm[pad(t * PER + j)] = r[j];
    __syncthreads();
#pragma unroll
    for (int j = 0; j < PER; j++) r[j] = sm[pad(j * NT + t)];

    // Remaining i-bits 9..11 = register-index bits 1..3
    reg_stage(r, 2); reg_stage(r, 4); reg_stage(r, 8);

    // Store, fused *s1. Coalesced.
#pragma unroll
    for (int j = 0; j < PER; j++) {
        int i = j * NT + t;
        orow[i] = r[j] * __ldg(&s1[i]);
    }
}

extern "C" void kernel_launch(void* const* d_in, const int* in_sizes, int n_in,
                              void* d_out, int out_size) {
    const float* x     = (const float*)d_in[0];
    const float* s1    = (const float*)d_in[1];
    const float* s2    = (const float*)d_in[2];
    const float* g_mu  = (const float*)d_in[3];
    const float* g_rho = (const float*)d_in[4];
    const float* eps   = (const float*)d_in[5];
    float* out = (float*)d_out;

    prep_g_kernel<<<(D + 255) / 256, 256>>>(g_mu, g_rho, eps);
    whvi_kernel<<<NROWS, NT>>>(x, s1, s2, out);
}

// round 8
// speedup vs baseline: 1.3082x; 1.3082x over previous
#include <cuda_runtime.h>

#define NROWS 8192
#define D     4096
#define NT    256
#define PER   16   // elements per thread

// Precomputed g = g_mu + softplus(g_rho) * epsilon (same for every row)
__device__ float g_buf[D];

__global__ void prep_g_kernel(const float* __restrict__ g_mu,
                              const float* __restrict__ g_rho,
                              const float* __restrict__ eps) {
    int i = blockIdx.x * blockDim.x + threadIdx.x;
    if (i < D) {
        float x  = g_rho[i];
        float sp = fmaxf(x, 0.0f) + log1pf(expf(-fabsf(x)));
        g_buf[i] = g_mu[i] + sp * eps[i];
    }
}

// ---- SMEM XOR swizzles: bijections on [0,4096), conflict-free per pattern ----
// B<->C transposes. Injects i[5],i[6] into bits 2,3 and i[8] into bit 4.
//   B-side 128-bit: group bits[2:4] = (k0^l1, k1^l2, l0^l4) -> 8 distinct per phase.
//   C-side scalar:  bank = (l0, l1, l2^j1, l3^j2, j0^l4) -> 32 distinct lanes.
__device__ __forceinline__ int addrBC(int i) {
    return i ^ (((i >> 5) & 3) << 2) ^ (((i >> 8) & 1) << 4);
}
// C<->A transposes. Injects i[8] into bit 4.
//   C-side scalar: bank = (l0..l3, j0^l4) -> 32 distinct.
//   A-side scalar: swizzle source i[8]=j0 const per instr -> bank = l -> 32 distinct.
__device__ __forceinline__ int addrCA(int i) {
    return i ^ (((i >> 8) & 1) << 4);
}

// Butterfly over a register-index bit (stages commute; reg bits always map to
// 4 consecutive i-bits in each layout).
__device__ __forceinline__ void reg_stage(float* r, int bit) {
#pragma unroll
    for (int j = 0; j < PER; j++) {
        if (!(j & bit)) {
            float a = r[j], b = r[j | bit];
            r[j]       = a + b;
            r[j | bit] = a - b;
        }
    }
}

__device__ __forceinline__ void four_stages(float* r) {
    reg_stage(r, 1); reg_stage(r, 2); reg_stage(r, 4); reg_stage(r, 8);
}

__global__ __launch_bounds__(NT) void whvi_kernel(const float* __restrict__ x,
                                                  const float* __restrict__ s1,
                                                  const float* __restrict__ s2,
                                                  float* __restrict__ out) {
    __shared__ float sm[D];   // 16KB; swizzles are bijections on [0,D)

    const int t  = threadIdx.x;
    const int tl = t & 15;   // t[0:4]
    const int th = t >> 4;   // t[4:8]
    const size_t rowoff = (size_t)blockIdx.x * D;

    const float4* __restrict__ x4  = (const float4*)(x + rowoff);
    const float4* __restrict__ s2v = (const float4*)s2;
    const float4* __restrict__ s1v = (const float4*)s1;
    float4* __restrict__ o4 = (float4*)(out + rowoff);

    float r[PER];

    // ---- Load layout B (i = 16t + j): vectorized, fused *s2 ----
#pragma unroll
    for (int k = 0; k < 4; k++) {
        float4 v = x4[t * 4 + k];
        float4 s = __ldg(&s2v[t * 4 + k]);
        r[4 * k + 0] = v.x * s.x;
        r[4 * k + 1] = v.y * s.y;
        r[4 * k + 2] = v.z * s.z;
        r[4 * k + 3] = v.w * s.w;
    }

    // ================= FWHT #1 =================
    four_stages(r);                      // i-bits 0-3 (layout B)

    // T1: B -> C (write 128-bit, read scalar)
#pragma unroll
    for (int k = 0; k < 4; k++) {
        float4 v = make_float4(r[4 * k], r[4 * k + 1], r[4 * k + 2], r[4 * k + 3]);
        *(float4*)&sm[addrBC(16 * t + 4 * k)] = v;    // STS.128
    }
    __syncthreads();
#pragma unroll
    for (int j = 0; j < PER; j++)
        r[j] = sm[addrBC(tl + j * 16 + th * 256)];    // LDS.32

    four_stages(r);                      // i-bits 4-7 (layout C)

    // T2: C -> A
    __syncthreads();                     // all T1 reads done before overwrite
#pragma unroll
    for (int j = 0; j < PER; j++)
        sm[addrCA(tl + j * 16 + th * 256)] = r[j];
    __syncthreads();
#pragma unroll
    for (int j = 0; j < PER; j++)
        r[j] = sm[addrCA(j * 256 + t)];

    four_stages(r);                      // i-bits 8-11 (layout A)

    // ---- elementwise * g (layout A: lane-coalesced, L2-resident) ----
#pragma unroll
    for (int j = 0; j < PER; j++)
        r[j] *= g_buf[j * 256 + t];

    // ================= FWHT #2 =================
    four_stages(r);                      // i-bits 8-11 (layout A)

    // T3: A -> C
    __syncthreads();                     // all T2 reads done before overwrite
#pragma unroll
    for (int j = 0; j < PER; j++)
        sm[addrCA(j * 256 + t)] = r[j];
    __syncthreads();
#pragma unroll
    for (int j = 0; j < PER; j++)
        r[j] = sm[addrCA(tl + j * 16 + th * 256)];

    four_stages(r);                      // i-bits 4-7 (layout C)

    // T4: C -> B (write scalar, read 128-bit)
    __syncthreads();                     // all T3 reads done before overwrite
#pragma unroll
    for (int j = 0; j < PER; j++)
        sm[addrBC(tl + j * 16 + th * 256)] = r[j];
    __syncthreads();
#pragma unroll
    for (int k = 0; k < 4; k++) {
        float4 v = *(const float4*)&sm[addrBC(16 * t + 4 * k)];   // LDS.128
        r[4 * k + 0] = v.x; r[4 * k + 1] = v.y;
        r[4 * k + 2] = v.z; r[4 * k + 3] = v.w;
    }

    four_stages(r);                      // i-bits 0-3 (layout B)

    // ---- Store layout B: vectorized, fused *s1 ----
#pragma unroll
    for (int k = 0; k < 4; k++) {
        float4 s = __ldg(&s1v[t * 4 + k]);
        float4 v;
        v.x = r[4 * k + 0] * s.x;
        v.y = r[4 * k + 1] * s.y;
        v.z = r[4 * k + 2] * s.z;
        v.w = r[4 * k + 3] * s.w;
        o4[t * 4 + k] = v;
    }
}

extern "C" void kernel_launch(void* const* d_in, const int* in_sizes, int n_in,
                              void* d_out, int out_size) {
    const float* x     = (const float*)d_in[0];
    const float* s1    = (const float*)d_in[1];
    const float* s2    = (const float*)d_in[2];
    const float* g_mu  = (const float*)d_in[3];
    const float* g_rho = (const float*)d_in[4];
    const float* eps   = (const float*)d_in[5];
    float* out = (float*)d_out;

    prep_g_kernel<<<(D + 255) / 256, 256>>>(g_mu, g_rho, eps);
    whvi_kernel<<<NROWS, NT>>>(x, s1, s2, out);
}

// round 12
// speedup vs baseline: 1.3540x; 1.0350x over previous
#include <cuda_runtime.h>

#define NROWS 8192
#define D     4096
#define NT    256
#define PER   16   // elements per thread

// Packed g pairs for the layout-A multiply:
// g2[k*256 + t] = ( g[(2k)*256 + t], g[(2k+1)*256 + t] ),  g = g_mu + softplus(g_rho)*eps
__device__ float2 g2[D / 2];

__global__ void prep_g_kernel(const float* __restrict__ g_mu,
                              const float* __restrict__ g_rho,
                              const float* __restrict__ eps) {
    int u = blockIdx.x * blockDim.x + threadIdx.x;   // [0, 2048)
    if (u < D / 2) {
        int t  = u & 255;
        int k  = u >> 8;
        int i0 = k * 512 + t;        // element (2k)*256 + t
        int i1 = i0 + 256;           // element (2k+1)*256 + t
        float x0 = g_rho[i0], x1 = g_rho[i1];
        float sp0 = fmaxf(x0, 0.0f) + log1pf(expf(-fabsf(x0)));
        float sp1 = fmaxf(x1, 0.0f) + log1pf(expf(-fabsf(x1)));
        g2[u] = make_float2(g_mu[i0] + sp0 * eps[i0],
                            g_mu[i1] + sp1 * eps[i1]);
    }
}

// ---- SMEM XOR swizzles: bijections on [0,4096), conflict-free per pattern ----
__device__ __forceinline__ int addrBC(int i) {
    return i ^ (((i >> 5) & 3) << 2) ^ (((i >> 8) & 1) << 4);
}
__device__ __forceinline__ int addrCA(int i) {
    return i ^ (((i >> 8) & 1) << 4);
}

// ---- packed f32x2 primitives ----
// Butterfly between pairs (r[a],r[a+1]) and (r[b],r[b+1]):
//   (pa, pb) <- (pa + pb, pa - pb)   [2 packed ops: add.f32x2 + fma.f32x2 with -1]
__device__ __forceinline__ void bf_pair(float* r, int a, int b, unsigned long long neg1) {
    float ax = r[a], ay = r[a + 1], bx = r[b], by = r[b + 1];
    asm("{\n\t"
        ".reg .b64 ra, rb, rs, rd;\n\t"
        "mov.b64 ra, {%4,%5};\n\t"
        "mov.b64 rb, {%6,%7};\n\t"
        "add.rn.f32x2 rs, ra, rb;\n\t"
        "fma.rn.f32x2 rd, rb, %8, ra;\n\t"
        "mov.b64 {%0,%1}, rs;\n\t"
        "mov.b64 {%2,%3}, rd;\n\t"
        "}"
        : "=f"(r[a]), "=f"(r[a + 1]), "=f"(r[b]), "=f"(r[b + 1])
        : "f"(ax), "f"(ay), "f"(bx), "f"(by), "l"(neg1));
}

// Packed multiply: (ox,oy) = (ax,ay) * (bx,by)
__device__ __forceinline__ void pk_mul2(float& ox, float& oy,
                                        float ax, float ay, float bx, float by) {
    asm("{\n\t"
        ".reg .b64 ra, rb, rd;\n\t"
        "mov.b64 ra, {%2,%3};\n\t"
        "mov.b64 rb, {%4,%5};\n\t"
        "mul.rn.f32x2 rd, ra, rb;\n\t"
        "mov.b64 {%0,%1}, rd;\n\t"
        "}"
        : "=f"(ox), "=f"(oy) : "f"(ax), "f"(ay), "f"(bx), "f"(by));
}

// Four FWHT stages over the 4 register-index bits.
// Stage bit0: scalar within each (2k,2k+1) pair. Stages bit1..3: packed across pairs.
__device__ __forceinline__ void four_stages(float* r, unsigned long long neg1) {
#pragma unroll
    for (int k = 0; k < 8; k++) {
        float a = r[2 * k], b = r[2 * k + 1];
        r[2 * k]     = a + b;
        r[2 * k + 1] = a - b;
    }
#pragma unroll
    for (int pm = 1; pm <= 4; pm <<= 1) {
#pragma unroll
        for (int k = 0; k < 8; k++) {
            if (!(k & pm)) bf_pair(r, 2 * k, 2 * (k | pm), neg1);
        }
    }
}

__global__ __launch_bounds__(NT) void whvi_kernel(const float* __restrict__ x,
                                                  const float* __restrict__ s1,
                                                  const float* __restrict__ s2,
                                                  float* __restrict__ out) {
    __shared__ float sm[D];   // 16KB; swizzles are bijections on [0,D)

    const unsigned long long NEG1 = 0xBF800000BF800000ULL;  // (-1.0f, -1.0f)

    const int t  = threadIdx.x;
    const int tl = t & 15;   // t[0:4]
    const int th = t >> 4;   // t[4:8]
    const size_t rowoff = (size_t)blockIdx.x * D;

    const float4* __restrict__ x4  = (const float4*)(x + rowoff);
    const float4* __restrict__ s2v = (const float4*)s2;
    const float4* __restrict__ s1v = (const float4*)s1;
    float4* __restrict__ o4 = (float4*)(out + rowoff);

    float r[PER];

    // ---- Load layout B (i = 16t + j): vectorized, fused *s2 (packed) ----
#pragma unroll
    for (int k = 0; k < 4; k++) {
        float4 v = x4[t * 4 + k];
        float4 s = __ldg(&s2v[t * 4 + k]);
        pk_mul2(r[4 * k + 0], r[4 * k + 1], v.x, v.y, s.x, s.y);
        pk_mul2(r[4 * k + 2], r[4 * k + 3], v.z, v.w, s.z, s.w);
    }

    // ================= FWHT #1 =================
    four_stages(r, NEG1);                // i-bits 0-3 (layout B)

    // T1: B -> C (write 128-bit, read scalar)
#pragma unroll
    for (int k = 0; k < 4; k++) {
        float4 v = make_float4(r[4 * k], r[4 * k + 1], r[4 * k + 2], r[4 * k + 3]);
        *(float4*)&sm[addrBC(16 * t + 4 * k)] = v;    // STS.128
    }
    __syncthreads();
#pragma unroll
    for (int j = 0; j < PER; j++)
        r[j] = sm[addrBC(tl + j * 16 + th * 256)];    // LDS.32

    four_stages(r, NEG1);                // i-bits 4-7 (layout C)

    // T2: C -> A
    __syncthreads();                     // all T1 reads done before overwrite
#pragma unroll
    for (int j = 0; j < PER; j++)
        sm[addrCA(tl + j * 16 + th * 256)] = r[j];
    __syncthreads();
#pragma unroll
    for (int j = 0; j < PER; j++)
        r[j] = sm[addrCA(j * 256 + t)];

    four_stages(r, NEG1);                // i-bits 8-11 (layout A)

    // ---- elementwise * g (layout A, packed pairs; L2-resident) ----
#pragma unroll
    for (int k = 0; k < 8; k++) {
        float2 gv = g2[k * 256 + t];     // LDG.64, lane-coalesced
        pk_mul2(r[2 * k], r[2 * k + 1], r[2 * k], r[2 * k + 1], gv.x, gv.y);
    }

    // ================= FWHT #2 =================
    four_stages(r, NEG1);                // i-bits 8-11 (layout A)

    // T3: A -> C
    __syncthreads();                     // all T2 reads done before overwrite
#pragma unroll
    for (int j = 0; j < PER; j++)
        sm[addrCA(j * 256 + t)] = r[j];
    __syncthreads();
#pragma unroll
    for (int j = 0; j < PER; j++)
        r[j] = sm[addrCA(tl + j * 16 + th * 256)];

    four_stages(r, NEG1);                // i-bits 4-7 (layout C)

    // T4: C -> B (write scalar, read 128-bit)
    __syncthreads();                     // all T3 reads done before overwrite
#pragma unroll
    for (int j = 0; j < PER; j++)
        sm[addrBC(tl + j * 16 + th * 256)] = r[j];
    __syncthreads();
#pragma unroll
    for (int k = 0; k < 4; k++) {
        float4 v = *(const float4*)&sm[addrBC(16 * t + 4 * k)];   // LDS.128
        r[4 * k + 0] = v.x; r[4 * k + 1] = v.y;
        r[4 * k + 2] = v.z; r[4 * k + 3] = v.w;
    }

    four_stages(r, NEG1);                // i-bits 0-3 (layout B)

    // ---- Store layout B: vectorized, fused *s1 (packed) ----
#pragma unroll
    for (int k = 0; k < 4; k++) {
        float4 s = __ldg(&s1v[t * 4 + k]);
        float4 v;
        pk_mul2(v.x, v.y, r[4 * k + 0], r[4 * k + 1], s.x, s.y);
        pk_mul2(v.z, v.w, r[4 * k + 2], r[4 * k + 3], s.z, s.w);
        o4[t * 4 + k] = v;
    }
}

extern "C" void kernel_launch(void* const* d_in, const int* in_sizes, int n_in,
                              void* d_out, int out_size) {
    const float* x     = (const float*)d_in[0];
    const float* s1    = (const float*)d_in[1];
    const float* s2    = (const float*)d_in[2];
    const float* g_mu  = (const float*)d_in[3];
    const float* g_rho = (const float*)d_in[4];
    const float* eps   = (const float*)d_in[5];
    float* out = (float*)d_out;

    prep_g_kernel<<<(D / 2 + 255) / 256, 256>>>(g_mu, g_rho, eps);
    whvi_kernel<<<NROWS, NT>>>(x, s1, s2, out);
}

// round 13
// speedup vs baseline: 2.1264x; 1.5705x over previous
#include <cuda_runtime.h>

#define NROWS 8192
#define D     4096
#define NT    64
#define PER   64   // elements per thread; 6 reg bits per layout, 2 layouts = 12 bits

// g permuted into layout-B'' order, packed float4:
// g4[jq*64 + t].c = g[(t&3) + 4*(4*jq+c) + 256*(t>>2)],  g = g_mu + softplus(g_rho)*eps
__device__ float4 g4[D / 4];

__global__ void prep_g_kernel(const float* __restrict__ g_mu,
                              const float* __restrict__ g_rho,
                              const float* __restrict__ eps) {
    int u = blockIdx.x * blockDim.x + threadIdx.x;   // [0, 1024)
    if (u < D / 4) {
        int t  = u & 63;
        int jq = u >> 6;
        float4 o;
        float* op = (float*)&o;
#pragma unroll
        for (int c = 0; c < 4; c++) {
            int j = 4 * jq + c;
            int i = (t & 3) + 4 * j + 256 * (t >> 2);
            float x  = g_rho[i];
            float sp = fmaxf(x, 0.0f) + log1pf(expf(-fabsf(x)));
            op[c] = g_mu[i] + sp * eps[i];
        }
        g4[u] = o;
    }
}

// SMEM swizzle: bijection on [0,4096). Bits 2-4 ^= bits 8-10.
//  A'-side 128-bit (word = 256k+4t): 16B-group bits = t0t1t2 ^ k0k1k2(const) -> 8 distinct/phase.
//  B''-side scalar (word = t01 + 4j + 256*t[2:6]): bank = (t0,t1,j0^t2,j1^t3,j2^t4) -> 32 distinct.
__device__ __forceinline__ int sw(int i) {
    return i ^ (((i >> 8) & 7) << 2);
}

// ---- packed f32x2 primitives ----
__device__ __forceinline__ void bf_pair(float* r, int a, int b, unsigned long long neg1) {
    float ax = r[a], ay = r[a + 1], bx = r[b], by = r[b + 1];
    asm("{\n\t"
        ".reg .b64 ra, rb, rs, rd;\n\t"
        "mov.b64 ra, {%4,%5};\n\t"
        "mov.b64 rb, {%6,%7};\n\t"
        "add.rn.f32x2 rs, ra, rb;\n\t"
        "fma.rn.f32x2 rd, rb, %8, ra;\n\t"
        "mov.b64 {%0,%1}, rs;\n\t"
        "mov.b64 {%2,%3}, rd;\n\t"
        "}"
        : "=f"(r[a]), "=f"(r[a + 1]), "=f"(r[b]), "=f"(r[b + 1])
        : "f"(ax), "f"(ay), "f"(bx), "f"(by), "l"(neg1));
}

__device__ __forceinline__ void pk_mul2(float& ox, float& oy,
                                        float ax, float ay, float bx, float by) {
    asm("{\n\t"
        ".reg .b64 ra, rb, rd;\n\t"
        "mov.b64 ra, {%2,%3};\n\t"
        "mov.b64 rb, {%4,%5};\n\t"
        "mul.rn.f32x2 rd, ra, rb;\n\t"
        "mov.b64 {%0,%1}, rd;\n\t"
        "}"
        : "=f"(ox), "=f"(oy) : "f"(ax), "f"(ay), "f"(bx), "f"(by));
}

// Six FWHT stages over the 6 register-index bits of r[64].
// Reg bit 0: scalar intra-pair stage. Reg bits 1-5: packed across pairs.
__device__ __forceinline__ void six_stages(float* r, unsigned long long neg1) {
#pragma unroll
    for (int m = 0; m < 32; m++) {
        float a = r[2 * m], b = r[2 * m + 1];
        r[2 * m]     = a + b;
        r[2 * m + 1] = a - b;
    }
#pragma unroll
    for (int pb = 1; pb <= 16; pb <<= 1) {
#pragma unroll
        for (int m = 0; m < 32; m++) {
            if (!(m & pb)) bf_pair(r, 2 * m, 2 * (m | pb), neg1);
        }
    }
}

__global__ __launch_bounds__(NT, 8) void whvi_kernel(const float* __restrict__ x,
                                                     const float* __restrict__ s1,
                                                     const float* __restrict__ s2,
                                                     float* __restrict__ out) {
    __shared__ float sm[D];   // 16KB

    const unsigned long long NEG1 = 0xBF800000BF800000ULL;  // (-1.0f, -1.0f)

    const int t = threadIdx.x;                     // 6 bits
    const int bB = (t & 3) + 256 * (t >> 2);       // B'' base: i = bB + 4j
    const size_t rowoff = (size_t)blockIdx.x * D;

    const float4* __restrict__ x4  = (const float4*)(x + rowoff);
    const float4* __restrict__ s2v = (const float4*)s2;
    const float4* __restrict__ s1v = (const float4*)s1;
    float4* __restrict__ o4 = (float4*)(out + rowoff);

    float r[PER];

    // ---- Load layout A' (r[4k+c] = i = 256k+4t+c): coalesced float4, fused *s2 ----
#pragma unroll
    for (int k = 0; k < 16; k++) {
        float4 v = x4[64 * k + t];
        float4 s = __ldg(&s2v[64 * k + t]);
        pk_mul2(r[4 * k + 0], r[4 * k + 1], v.x, v.y, s.x, s.y);
        pk_mul2(r[4 * k + 2], r[4 * k + 3], v.z, v.w, s.z, s.w);
    }

    // FWHT#1 part 1: i-bits {0,1,8,9,10,11} (layout A')
    six_stages(r, NEG1);

    // T1: A' -> B''  (write 128-bit, read scalar)
#pragma unroll
    for (int k = 0; k < 16; k++) {
        float4 v = make_float4(r[4 * k], r[4 * k + 1], r[4 * k + 2], r[4 * k + 3]);
        *(float4*)&sm[sw(256 * k + 4 * t)] = v;          // STS.128
    }
    __syncthreads();
#pragma unroll
    for (int j = 0; j < PER; j++)
        r[j] = sm[sw(bB + 4 * j)];                       // LDS.32

    // FWHT#1 part 2: i-bits {2..7} (layout B'')
    six_stages(r, NEG1);

    // ---- elementwise * g (layout B'', pre-permuted, coalesced float4) ----
#pragma unroll
    for (int jq = 0; jq < 16; jq++) {
        float4 gv = g4[jq * 64 + t];
        pk_mul2(r[4 * jq + 0], r[4 * jq + 1], r[4 * jq + 0], r[4 * jq + 1], gv.x, gv.y);
        pk_mul2(r[4 * jq + 2], r[4 * jq + 3], r[4 * jq + 2], r[4 * jq + 3], gv.z, gv.w);
    }

    // FWHT#2 part 1: i-bits {2..7} (layout B'')
    six_stages(r, NEG1);

    // T2: B'' -> A'  (write scalar, read 128-bit)
    __syncthreads();                                     // all T1 reads done
#pragma unroll
    for (int j = 0; j < PER; j++)
        sm[sw(bB + 4 * j)] = r[j];                       // STS.32
    __syncthreads();
#pragma unroll
    for (int k = 0; k < 16; k++) {
        float4 v = *(const float4*)&sm[sw(256 * k + 4 * t)];  // LDS.128
        r[4 * k + 0] = v.x; r[4 * k + 1] = v.y;
        r[4 * k + 2] = v.z; r[4 * k + 3] = v.w;
    }

    // FWHT#2 part 2: i-bits {0,1,8,9,10,11} (layout A')
    six_stages(r, NEG1);

    // ---- Store layout A': coalesced float4, fused *s1 ----
#pragma unroll
    for (int k = 0; k < 16; k++) {
        float4 s = __ldg(&s1v[64 * k + t]);
        float4 v;
        pk_mul2(v.x, v.y, r[4 * k + 0], r[4 * k + 1], s.x, s.y);
        pk_mul2(v.z, v.w, r[4 * k + 2], r[4 * k + 3], s.z, s.w);
        o4[64 * k + t] = v;
    }
}

extern "C" void kernel_launch(void* const* d_in, const int* in_sizes, int n_in,
                              void* d_out, int out_size) {
    const float* x     = (const float*)d_in[0];
    const float* s1    = (const float*)d_in[1];
    const float* s2    = (const float*)d_in[2];
    const float* g_mu  = (const float*)d_in[3];
    const float* g_rho = (const float*)d_in[4];
    const float* eps   = (const float*)d_in[5];
    float* out = (float*)d_out;

    prep_g_kernel<<<(D / 4 + 255) / 256, 256>>>(g_mu, g_rho, eps);
    whvi_kernel<<<NROWS, NT>>>(x, s1, s2, out);
}